// round 12
// baseline (speedup 1.0000x reference)
#include <cuda_runtime.h>
#include <cuda_fp16.h>
#include <math.h>
#include <stdint.h>

#define N_NODES 50000
#define D_IN    768
#define NHID    256
#define ECAP    128                      // slots per row-bucket (P(overflow) ~ e^-49)

// ---------------- device scratch (no allocations allowed) ----------------
__device__ __half g_C1h[(size_t)N_NODES * 512];  // branch features (r1 0..255, r2 256..511), fp16
__device__ float  g_C1m[(size_t)N_NODES * 256];  // tanh mlp branch, fp32
__device__ float  g_Z2[(size_t)N_NODES * 4];     // x1 @ [W2r1 | W2r2]
__device__ float  g_W2[256 * 6];                 // packed layer-2 weights (row = hidden unit)

// fp16 operands for the tensor-core GEMM (both rounded to fp16)
__device__ __half g_xh[(size_t)N_NODES * 768];
__device__ __half g_Whi[768 * 768];              // transposed: [n][k] = Wcat[k][n]

// bucketed-CSR edge storage
__device__ int    g_cnt_adj[N_NODES];
__device__ int    g_cnt_s[N_NODES];
__device__ float2 g_edge_adj[(size_t)N_NODES * ECAP];   // .x = col (int bits), .y = val
__device__ float2 g_edge_s[(size_t)N_NODES * ECAP];

// ================= helpers =================
__device__ __forceinline__ uint32_t smem_u32(const void* p) {
    uint32_t a;
    asm("{ .reg .u64 t; cvta.to.shared.u64 t, %1; cvt.u32.u64 %0, t; }" : "=r"(a) : "l"(p));
    return a;
}
__device__ __forceinline__ void cp16(uint32_t dst, const void* src) {
    asm volatile("cp.async.cg.shared.global [%0], [%1], 16;" :: "r"(dst), "l"(src));
}
__device__ __forceinline__ void ldsm_x4(uint32_t* r, uint32_t addr) {
    asm volatile("ldmatrix.sync.aligned.m8n8.x4.shared.b16 {%0,%1,%2,%3}, [%4];"
                 : "=r"(r[0]), "=r"(r[1]), "=r"(r[2]), "=r"(r[3]) : "r"(addr));
}
__device__ __forceinline__ void mma_f16(float* c, const uint32_t* a, const uint32_t* b) {
    asm volatile("mma.sync.aligned.m16n8k16.row.col.f32.f16.f16.f32 "
                 "{%0,%1,%2,%3}, {%4,%5,%6,%7}, {%8,%9}, {%0,%1,%2,%3};"
                 : "+f"(c[0]), "+f"(c[1]), "+f"(c[2]), "+f"(c[3])
                 : "r"(a[0]), "r"(a[1]), "r"(a[2]), "r"(a[3]), "r"(b[0]), "r"(b[1]));
}

// ---------------- zero edge counters (must precede prep_all) ----------------
__global__ void zero_cnt() {
    int i = blockIdx.x * blockDim.x + threadIdx.x;
    if (i < N_NODES) { g_cnt_adj[i] = 0; g_cnt_s[i] = 0; }
}

// ---------------- fused prep: pack W1, pack W2, split x, build buckets ----------------
#define PW1_BLOCKS 2304                  // 768*768/256
#define PW2_BLOCKS 6                     // ceil(1536/256)
#define SPLIT_BLOCKS 1184
#define PREP_FIXED (PW1_BLOCKS + PW2_BLOCKS + SPLIT_BLOCKS)   // 3494

__global__ void prep_all(const float* __restrict__ x,
                         const float* __restrict__ W1r1,
                         const float* __restrict__ W1r2,
                         const float* __restrict__ mlp1_W,
                         const float* __restrict__ W2r1,
                         const float* __restrict__ W2r2,
                         const float* __restrict__ mlp2_W,
                         const int* __restrict__ adj_rows,
                         const int* __restrict__ adj_cols,
                         const float* __restrict__ adj_vals,
                         const int* __restrict__ s_rows,
                         const int* __restrict__ s_cols,
                         const float* __restrict__ s_vals,
                         int E) {
    const int b = blockIdx.x;
    const int tid = threadIdx.x;

    if (b < PW1_BLOCKS) {
        // pack + transpose layer-1 weights to fp16
        int idx = b * 256 + tid;
        int n = idx / 768, k = idx % 768;   // output [n][k] = W[k][n]
        float v;
        if (n < 256)       v = W1r1[k * 256 + n];
        else if (n < 512)  v = W1r2[k * 256 + (n - 256)];
        else               v = mlp1_W[k * 256 + (n - 512)];
        g_Whi[idx] = __float2half_rn(v);
    } else if (b < PW1_BLOCKS + PW2_BLOCKS) {
        int idx = (b - PW1_BLOCKS) * 256 + tid;
        if (idx < 256 * 6) {
            int k = idx / 6, j = idx % 6;
            float v;
            if (j < 2)      v = W2r1[k * 2 + j];
            else if (j < 4) v = W2r2[k * 2 + (j - 2)];
            else            v = mlp2_W[k * 2 + (j - 4)];
            g_W2[idx] = v;
        }
    } else if (b < PREP_FIXED) {
        // x -> fp16, vectorized grid-stride
        size_t i = (size_t)(b - PW1_BLOCKS - PW2_BLOCKS) * 256 + tid;
        const size_t stride = (size_t)SPLIT_BLOCKS * 256;
        const size_t total4 = (size_t)N_NODES * 768 / 4;
        const float4* x4 = reinterpret_cast<const float4*>(x);
        __half2* out2 = reinterpret_cast<__half2*>(g_xh);
        for (size_t j = i; j < total4; j += stride) {
            float4 v = x4[j];
            out2[2 * j + 0] = __floats2half2_rn(v.x, v.y);
            out2[2 * j + 1] = __floats2half2_rn(v.z, v.w);
        }
    } else {
        // build row buckets (counters pre-zeroed by zero_cnt)
        int idx = (b - PREP_FIXED) * 256 + tid;
        if (idx < E) {
            int r = adj_rows[idx];
            int slot = atomicAdd(&g_cnt_adj[r], 1);
            if (slot < ECAP)
                g_edge_adj[(size_t)r * ECAP + slot] =
                    make_float2(__int_as_float(adj_cols[idx]), adj_vals[idx]);
        } else if (idx < 2 * E) {
            int j = idx - E;
            int r = s_rows[j];
            int slot = atomicAdd(&g_cnt_s[r], 1);
            if (slot < ECAP)
                g_edge_s[(size_t)r * ECAP + slot] =
                    make_float2(__int_as_float(s_cols[j]), s_vals[j]);
        }
    }
}

// ================= GEMM1 via mma.sync (HMMA fp16, single product, BK=32) =================
#define BKC 32
#define ROWB 80                         // 64B data + 16B pad
#define GTILE (128 * ROWB)              // 10240 B per operand tile
#define GSTAGE (2 * GTILE)              // A, Whi = 20480 B
#define NSTAGE 4
#define GSMEM  (NSTAGE * GSTAGE)        // 81920 B
#define NCHUNK (768 / BKC)              // 24

__global__ __launch_bounds__(256, 2)
void gemm1_mma(const float* __restrict__ mlp1_b, int M) {
    extern __shared__ char dsm[];
    const uint32_t base = smem_u32(dsm);

    const int tid = threadIdx.x;
    const int lane = tid & 31, wid = tid >> 5;
    const int warp_m = wid >> 2;
    const int warp_n = wid & 3;
    const int tileM = blockIdx.y * 128;
    const int nBase = blockIdx.x * 128;

    const int ldRow = tid >> 2;
    const int ldC = tid & 3;
    int rA0 = tileM + ldRow;      if (rA0 >= M) rA0 = M - 1;
    int rA1 = tileM + ldRow + 64; if (rA1 >= M) rA1 = M - 1;
    const uint32_t ldDst0 = ldRow * ROWB + ldC * 16;
    const uint32_t ldDst1 = (ldRow + 64) * ROWB + ldC * 16;
    const size_t aBase0 = (size_t)rA0 * 768 + ldC * 8;
    const size_t aBase1 = (size_t)rA1 * 768 + ldC * 8;
    const size_t bBase0 = (size_t)(nBase + ldRow) * 768 + ldC * 8;
    const size_t bBase1 = (size_t)(nBase + ldRow + 64) * 768 + ldC * 8;

    const int aRow = warp_m * 64 + (lane & 15);
    const uint32_t aSel = (uint32_t)((lane >> 4) * 16);
    uint32_t aOffB[4];
#pragma unroll
    for (int mi = 0; mi < 4; mi++) aOffB[mi] = (uint32_t)((aRow + mi * 16) * ROWB) + aSel;
    const int bN = warp_n * 32 + (lane & 7) + ((lane >> 4) << 3);
    const uint32_t bSel = (uint32_t)(((lane >> 3) & 1) * 16);
    uint32_t bOffB[2];
#pragma unroll
    for (int p = 0; p < 2; p++) bOffB[p] = (uint32_t)((bN + p * 16) * ROWB) + bSel;

    float acc[4][4][4];
#pragma unroll
    for (int mi = 0; mi < 4; mi++)
#pragma unroll
        for (int ni = 0; ni < 4; ni++)
#pragma unroll
            for (int r = 0; r < 4; r++) acc[mi][ni][r] = 0.f;

#pragma unroll
    for (int pc = 0; pc < 3; pc++) {
        uint32_t st = base + pc * GSTAGE;
        const size_t k0 = (size_t)pc * BKC;
        cp16(st + ldDst0,         g_xh  + aBase0 + k0);
        cp16(st + ldDst1,         g_xh  + aBase1 + k0);
        cp16(st + GTILE + ldDst0, g_Whi + bBase0 + k0);
        cp16(st + GTILE + ldDst1, g_Whi + bBase1 + k0);
        asm volatile("cp.async.commit_group;" ::: "memory");
    }

    for (int kc = 0; kc < NCHUNK; ++kc) {
        if (kc + 2 < NCHUNK) {
            asm volatile("cp.async.wait_group 2;" ::: "memory");
        } else if (kc + 1 < NCHUNK) {
            asm volatile("cp.async.wait_group 1;" ::: "memory");
        } else {
            asm volatile("cp.async.wait_group 0;" ::: "memory");
        }
        __syncthreads();

        if (kc + 3 < NCHUNK) {
            uint32_t st = base + ((kc + 3) % NSTAGE) * GSTAGE;
            const size_t k0 = (size_t)(kc + 3) * BKC;
            cp16(st + ldDst0,         g_xh  + aBase0 + k0);
            cp16(st + ldDst1,         g_xh  + aBase1 + k0);
            cp16(st + GTILE + ldDst0, g_Whi + bBase0 + k0);
            cp16(st + GTILE + ldDst1, g_Whi + bBase1 + k0);
            asm volatile("cp.async.commit_group;" ::: "memory");
        }

        const uint32_t stCur = base + (kc % NSTAGE) * GSTAGE;
#pragma unroll
        for (int ks = 0; ks < 2; ks++) {
            const uint32_t ko = ks * 32;
            uint32_t bh[2][4];
#pragma unroll
            for (int p = 0; p < 2; p++)
                ldsm_x4(bh[p], stCur + GTILE + bOffB[p] + ko);
#pragma unroll
            for (int mi = 0; mi < 4; mi++) {
                uint32_t ah[4];
                ldsm_x4(ah, stCur + aOffB[mi] + ko);
#pragma unroll
                for (int ni = 0; ni < 4; ni++) {
                    const int p = ni >> 1, h = (ni & 1) * 2;
                    mma_f16(acc[mi][ni], ah, &bh[p][h]);
                }
            }
        }
    }

    const bool isMlp = (nBase >= 512);
    const int rBase = tileM + warp_m * 64 + (lane >> 2);
    const int cBase = nBase + warp_n * 32 + 2 * (lane & 3);
#pragma unroll
    for (int mi = 0; mi < 4; mi++) {
#pragma unroll
        for (int half = 0; half < 2; half++) {
            const int row = rBase + mi * 16 + half * 8;
            if (row >= M) continue;
#pragma unroll
            for (int ni = 0; ni < 4; ni++) {
                const int col = cBase + ni * 8;
                float v0 = acc[mi][ni][half * 2 + 0];
                float v1 = acc[mi][ni][half * 2 + 1];
                if (isMlp) {
                    v0 = tanhf(v0 + mlp1_b[col - 512]);
                    v1 = tanhf(v1 + mlp1_b[col - 511]);
                    *reinterpret_cast<float2*>(g_C1m + (size_t)row * 256 + (col - 512)) =
                        make_float2(v0, v1);
                } else {
                    *reinterpret_cast<__half2*>(g_C1h + (size_t)row * 512 + col) =
                        __floats2half2_rn(v0, v1);
                }
            }
        }
    }
}

// ---------------- fused layer-1 agg + attention + layer-2 linear + out init ----------------
// 256 threads/node. Gather: t<128 -> v1 pair, t>=128 -> v2 pair. Then attention
// softmax, x1 per thread, z = x1 @ W2 block-reduced, out initialized.
__global__ __launch_bounds__(256)
void gather_att(const float* __restrict__ b1r1,
                const float* __restrict__ b1r2,
                const float* __restrict__ af,
                const float* __restrict__ b2r1,
                const float* __restrict__ b2r2,
                const float* __restrict__ mlp2_b,
                float* __restrict__ out) {
    const int i = blockIdx.x;
    const int t = threadIdx.x;
    const int lane = t & 31, warp = t >> 5;
    const int br = t >> 7;                // 0: adj/v1, 1: s/v2
    const int u = (t & 127) * 2;          // first of 2 hidden units

    __shared__ float sv[768];             // v1[0..255], v2[256..511], v3[512..767]
    __shared__ float red[8][3];
    __shared__ float red6[8][6];

    float s0 = 0.f, s1 = 0.f;
    {
        const int n = min(br ? g_cnt_s[i] : g_cnt_adj[i], ECAP);
        const float2* eb = (br ? g_edge_s : g_edge_adj) + (size_t)i * ECAP;
        const size_t colOff = (size_t)(br * 256 + u);
        for (int e = 0; e < n; e++) {
            float2 ev = __ldg(eb + e);
            int c = __float_as_int(ev.x);
            __half2 hv = __ldg(reinterpret_cast<const __half2*>(
                                   g_C1h + (size_t)c * 512 + colOff));
            float2 f = __half22float2(hv);
            s0 += ev.y * f.x;
            s1 += ev.y * f.y;
        }
        const float* bias = br ? b1r2 : b1r1;
        s0 += bias[u]; s1 += bias[u + 1];
    }
    float t0 = 0.f, t1 = 0.f;
    if (br == 0) {
        float2 v3p = *reinterpret_cast<const float2*>(g_C1m + (size_t)i * 256 + u);
        t0 = v3p.x; t1 = v3p.y;
        sv[512 + u] = t0; sv[513 + u] = t1;
    }
    sv[br * 256 + u] = s0;
    sv[br * 256 + u + 1] = s1;

    // partial attention logits
    const int r0 = br * 256 + u;
    float p0 = s0 * af[r0 * 3 + 0] + s1 * af[(r0 + 1) * 3 + 0];
    float p1 = s0 * af[r0 * 3 + 1] + s1 * af[(r0 + 1) * 3 + 1];
    float p2 = s0 * af[r0 * 3 + 2] + s1 * af[(r0 + 1) * 3 + 2];
    if (br == 0) {
        const int r3 = 512 + u;
        p0 += t0 * af[r3 * 3 + 0] + t1 * af[(r3 + 1) * 3 + 0];
        p1 += t0 * af[r3 * 3 + 1] + t1 * af[(r3 + 1) * 3 + 1];
        p2 += t0 * af[r3 * 3 + 2] + t1 * af[(r3 + 1) * 3 + 2];
    }

#pragma unroll
    for (int off = 16; off; off >>= 1) {
        p0 += __shfl_xor_sync(0xffffffffu, p0, off);
        p1 += __shfl_xor_sync(0xffffffffu, p1, off);
        p2 += __shfl_xor_sync(0xffffffffu, p2, off);
    }
    if (lane == 0) { red[warp][0] = p0; red[warp][1] = p1; red[warp][2] = p2; }
    __syncthreads();

    float a0 = 0.f, a1 = 0.f, a2 = 0.f;
#pragma unroll
    for (int w = 0; w < 8; w++) { a0 += red[w][0]; a1 += red[w][1]; a2 += red[w][2]; }

    a0 = fabsf(a0); a1 = fabsf(a1); a2 = fabsf(a2);
    float m = fmaxf(a0, fmaxf(a1, a2));
    float e0 = __expf(a0 - m), e1 = __expf(a1 - m), e2 = __expf(a2 - m);
    float inv = 1.0f / (e0 + e1 + e2);
    float w0 = e0 * inv, w1 = e1 * inv, w2 = e2 * inv;

    // x1 for this thread's unit
    const float x1t = sv[t] * w0 + sv[256 + t] * w1 + sv[512 + t] * w2;

    // layer-2 linear: z[j] = sum_t x1t * W2[t][j]
    float z[6];
#pragma unroll
    for (int j = 0; j < 6; j++) z[j] = x1t * __ldg(g_W2 + t * 6 + j);
#pragma unroll
    for (int off = 16; off; off >>= 1)
#pragma unroll
        for (int j = 0; j < 6; j++) z[j] += __shfl_xor_sync(0xffffffffu, z[j], off);
    if (lane == 0)
#pragma unroll
        for (int j = 0; j < 6; j++) red6[warp][j] = z[j];
    __syncthreads();

    if (t == 0) {
        float zz[6] = {0.f, 0.f, 0.f, 0.f, 0.f, 0.f};
#pragma unroll
        for (int w = 0; w < 8; w++)
#pragma unroll
            for (int j = 0; j < 6; j++) zz[j] += red6[w][j];
        float* zdst = g_Z2 + (size_t)i * 4;
        zdst[0] = zz[0]; zdst[1] = zz[1]; zdst[2] = zz[2]; zdst[3] = zz[3];
        out[i * 2 + 0] = b2r1[0] + b2r2[0] + tanhf(zz[4] + mlp2_b[0]);
        out[i * 2 + 1] = b2r1[1] + b2r2[1] + tanhf(zz[5] + mlp2_b[1]);
    }
}

// ---------------- layer-2 aggregation: warp-per-node gather, no atomics ----------------
__global__ __launch_bounds__(256)
void gather2_out(float* __restrict__ out, int M) {
    const int warp = threadIdx.x >> 5, lane = threadIdx.x & 31;
    const int i = blockIdx.x * 8 + warp;
    if (i >= M) return;

    float s0 = 0.f, s1 = 0.f;
    {
        const int n = min(g_cnt_adj[i], ECAP);
        const float2* eb = g_edge_adj + (size_t)i * ECAP;
        for (int e = lane; e < n; e += 32) {
            float2 ev = __ldg(eb + e);
            int c = __float_as_int(ev.x);
            float2 z = *reinterpret_cast<const float2*>(g_Z2 + (size_t)c * 4);
            s0 += ev.y * z.x;
            s1 += ev.y * z.y;
        }
    }
    {
        const int n = min(g_cnt_s[i], ECAP);
        const float2* eb = g_edge_s + (size_t)i * ECAP;
        for (int e = lane; e < n; e += 32) {
            float2 ev = __ldg(eb + e);
            int c = __float_as_int(ev.x);
            float2 z = *reinterpret_cast<const float2*>(g_Z2 + (size_t)c * 4 + 2);
            s0 += ev.y * z.x;
            s1 += ev.y * z.y;
        }
    }
#pragma unroll
    for (int off = 16; off; off >>= 1) {
        s0 += __shfl_xor_sync(0xffffffffu, s0, off);
        s1 += __shfl_xor_sync(0xffffffffu, s1, off);
    }
    if (lane == 0) {
        out[i * 2 + 0] += s0;
        out[i * 2 + 1] += s1;
    }
}

// ---------------- launch ----------------
extern "C" void kernel_launch(void* const* d_in, const int* in_sizes, int n_in,
                              void* d_out, int out_size) {
    const float* x        = (const float*)d_in[0];
    const int*   adj_rows = (const int*)d_in[1];
    const int*   adj_cols = (const int*)d_in[2];
    const float* adj_vals = (const float*)d_in[3];
    const int*   s_rows   = (const int*)d_in[4];
    const int*   s_cols   = (const int*)d_in[5];
    const float* s_vals   = (const float*)d_in[6];
    const float* W1r1     = (const float*)d_in[7];
    const float* b1r1     = (const float*)d_in[8];
    const float* W1r2     = (const float*)d_in[9];
    const float* b1r2     = (const float*)d_in[10];
    const float* mlp1_W   = (const float*)d_in[11];
    const float* mlp1_b   = (const float*)d_in[12];
    const float* af1_w    = (const float*)d_in[13];
    const float* W2r1     = (const float*)d_in[14];
    const float* b2r1     = (const float*)d_in[15];
    const float* W2r2     = (const float*)d_in[16];
    const float* b2r2     = (const float*)d_in[17];
    const float* mlp2_W   = (const float*)d_in[18];
    const float* mlp2_b   = (const float*)d_in[19];
    float* out = (float*)d_out;

    const int E = in_sizes[1];
    const int M = N_NODES;

    cudaFuncSetAttribute(gemm1_mma, cudaFuncAttributeMaxDynamicSharedMemorySize, GSMEM);

    // prep: counters first, then everything else fused in one wide kernel
    zero_cnt<<<(N_NODES + 255) / 256, 256>>>();
    const int bucketBlocks = (2 * E + 255) / 256;
    prep_all<<<PREP_FIXED + bucketBlocks, 256>>>(
        x, W1r1, W1r2, mlp1_W, W2r1, W2r2, mlp2_W,
        adj_rows, adj_cols, adj_vals, s_rows, s_cols, s_vals, E);

    // layer 1 big GEMM on tensor cores (HMMA fp16, single product)
    dim3 g1(6, (M + 127) / 128);
    gemm1_mma<<<g1, 256, GSMEM>>>(mlp1_b, M);

    // layer 1 aggregation + attention + layer-2 linear + out init (fused)
    gather_att<<<M, 256>>>(b1r1, b1r2, af1_w, b2r1, b2r2, mlp2_b, out);

    // layer-2 aggregation
    gather2_out<<<(M + 7) / 8, 256>>>(out, M);
}

// round 13
// speedup vs baseline: 1.1661x; 1.1661x over previous
#include <cuda_runtime.h>
#include <cuda_fp16.h>
#include <math.h>
#include <stdint.h>

#define N_NODES 50000
#define D_IN    768
#define NHID    256
#define ECAP    128                      // slots per row-bucket (P(overflow) ~ e^-49)

// ---------------- device scratch (no allocations allowed) ----------------
__device__ __half g_C1h[(size_t)N_NODES * 512];  // branch features (r1 0..255, r2 256..511), fp16
__device__ float  g_C1m[(size_t)N_NODES * 256];  // tanh mlp branch, fp32
__device__ float  g_X1[(size_t)N_NODES * 256];   // fused layer-1 output
__device__ float  g_Z2[(size_t)N_NODES * 4];     // x1 @ [W2r1 | W2r2]
__device__ float  g_W2[256 * 6];                 // packed layer-2 weights (row = hidden unit)

// fp16 operands for the tensor-core GEMM (both rounded to fp16)
__device__ __half g_xh[(size_t)N_NODES * 768];
__device__ __half g_Whi[768 * 768];              // transposed: [n][k] = Wcat[k][n]

// bucketed-CSR edge storage
__device__ int    g_cnt_adj[N_NODES];
__device__ int    g_cnt_s[N_NODES];
__device__ float2 g_edge_adj[(size_t)N_NODES * ECAP];   // .x = col (int bits), .y = val
__device__ float2 g_edge_s[(size_t)N_NODES * ECAP];

// ================= helpers =================
__device__ __forceinline__ uint32_t smem_u32(const void* p) {
    uint32_t a;
    asm("{ .reg .u64 t; cvta.to.shared.u64 t, %1; cvt.u32.u64 %0, t; }" : "=r"(a) : "l"(p));
    return a;
}
__device__ __forceinline__ void cp16(uint32_t dst, const void* src) {
    asm volatile("cp.async.cg.shared.global [%0], [%1], 16;" :: "r"(dst), "l"(src));
}
__device__ __forceinline__ void ldsm_x4(uint32_t* r, uint32_t addr) {
    asm volatile("ldmatrix.sync.aligned.m8n8.x4.shared.b16 {%0,%1,%2,%3}, [%4];"
                 : "=r"(r[0]), "=r"(r[1]), "=r"(r[2]), "=r"(r[3]) : "r"(addr));
}
__device__ __forceinline__ void mma_f16(float* c, const uint32_t* a, const uint32_t* b) {
    asm volatile("mma.sync.aligned.m16n8k16.row.col.f32.f16.f16.f32 "
                 "{%0,%1,%2,%3}, {%4,%5,%6,%7}, {%8,%9}, {%0,%1,%2,%3};"
                 : "+f"(c[0]), "+f"(c[1]), "+f"(c[2]), "+f"(c[3])
                 : "r"(a[0]), "r"(a[1]), "r"(a[2]), "r"(a[3]), "r"(b[0]), "r"(b[1]));
}

// ---------------- zero edge counters (must precede prep_all) ----------------
__global__ void zero_cnt() {
    int i = blockIdx.x * blockDim.x + threadIdx.x;
    if (i < N_NODES) { g_cnt_adj[i] = 0; g_cnt_s[i] = 0; }
}

// ---------------- fused prep: pack W1, pack W2, split x, build buckets ----------------
#define PW1_BLOCKS 2304                  // 768*768/256
#define PW2_BLOCKS 6
#define SPLIT_BLOCKS 1184
#define PREP_FIXED (PW1_BLOCKS + PW2_BLOCKS + SPLIT_BLOCKS)

__global__ void prep_all(const float* __restrict__ x,
                         const float* __restrict__ W1r1,
                         const float* __restrict__ W1r2,
                         const float* __restrict__ mlp1_W,
                         const float* __restrict__ W2r1,
                         const float* __restrict__ W2r2,
                         const float* __restrict__ mlp2_W,
                         const int* __restrict__ adj_rows,
                         const int* __restrict__ adj_cols,
                         const float* __restrict__ adj_vals,
                         const int* __restrict__ s_rows,
                         const int* __restrict__ s_cols,
                         const float* __restrict__ s_vals,
                         int E) {
    const int b = blockIdx.x;
    const int tid = threadIdx.x;

    if (b < PW1_BLOCKS) {
        int idx = b * 256 + tid;
        int n = idx / 768, k = idx % 768;   // output [n][k] = W[k][n]
        float v;
        if (n < 256)       v = W1r1[k * 256 + n];
        else if (n < 512)  v = W1r2[k * 256 + (n - 256)];
        else               v = mlp1_W[k * 256 + (n - 512)];
        g_Whi[idx] = __float2half_rn(v);
    } else if (b < PW1_BLOCKS + PW2_BLOCKS) {
        int idx = (b - PW1_BLOCKS) * 256 + tid;
        if (idx < 256 * 6) {
            int k = idx / 6, j = idx % 6;
            float v;
            if (j < 2)      v = W2r1[k * 2 + j];
            else if (j < 4) v = W2r2[k * 2 + (j - 2)];
            else            v = mlp2_W[k * 2 + (j - 4)];
            g_W2[idx] = v;
        }
    } else if (b < PREP_FIXED) {
        size_t i = (size_t)(b - PW1_BLOCKS - PW2_BLOCKS) * 256 + tid;
        const size_t stride = (size_t)SPLIT_BLOCKS * 256;
        const size_t total4 = (size_t)N_NODES * 768 / 4;
        const float4* x4 = reinterpret_cast<const float4*>(x);
        __half2* out2 = reinterpret_cast<__half2*>(g_xh);
        for (size_t j = i; j < total4; j += stride) {
            float4 v = x4[j];
            out2[2 * j + 0] = __floats2half2_rn(v.x, v.y);
            out2[2 * j + 1] = __floats2half2_rn(v.z, v.w);
        }
    } else {
        int idx = (b - PREP_FIXED) * 256 + tid;
        if (idx < E) {
            int r = adj_rows[idx];
            int slot = atomicAdd(&g_cnt_adj[r], 1);
            if (slot < ECAP)
                g_edge_adj[(size_t)r * ECAP + slot] =
                    make_float2(__int_as_float(adj_cols[idx]), adj_vals[idx]);
        } else if (idx < 2 * E) {
            int j = idx - E;
            int r = s_rows[j];
            int slot = atomicAdd(&g_cnt_s[r], 1);
            if (slot < ECAP)
                g_edge_s[(size_t)r * ECAP + slot] =
                    make_float2(__int_as_float(s_cols[j]), s_vals[j]);
        }
    }
}

// ================= GEMM1 via mma.sync (HMMA fp16, single product, BK=32) =================
#define BKC 32
#define ROWB 80
#define GTILE (128 * ROWB)
#define GSTAGE (2 * GTILE)
#define NSTAGE 4
#define GSMEM  (NSTAGE * GSTAGE)
#define NCHUNK (768 / BKC)

__global__ __launch_bounds__(256, 2)
void gemm1_mma(const float* __restrict__ mlp1_b, int M) {
    extern __shared__ char dsm[];
    const uint32_t base = smem_u32(dsm);

    const int tid = threadIdx.x;
    const int lane = tid & 31, wid = tid >> 5;
    const int warp_m = wid >> 2;
    const int warp_n = wid & 3;
    const int tileM = blockIdx.y * 128;
    const int nBase = blockIdx.x * 128;

    const int ldRow = tid >> 2;
    const int ldC = tid & 3;
    int rA0 = tileM + ldRow;      if (rA0 >= M) rA0 = M - 1;
    int rA1 = tileM + ldRow + 64; if (rA1 >= M) rA1 = M - 1;
    const uint32_t ldDst0 = ldRow * ROWB + ldC * 16;
    const uint32_t ldDst1 = (ldRow + 64) * ROWB + ldC * 16;
    const size_t aBase0 = (size_t)rA0 * 768 + ldC * 8;
    const size_t aBase1 = (size_t)rA1 * 768 + ldC * 8;
    const size_t bBase0 = (size_t)(nBase + ldRow) * 768 + ldC * 8;
    const size_t bBase1 = (size_t)(nBase + ldRow + 64) * 768 + ldC * 8;

    const int aRow = warp_m * 64 + (lane & 15);
    const uint32_t aSel = (uint32_t)((lane >> 4) * 16);
    uint32_t aOffB[4];
#pragma unroll
    for (int mi = 0; mi < 4; mi++) aOffB[mi] = (uint32_t)((aRow + mi * 16) * ROWB) + aSel;
    const int bN = warp_n * 32 + (lane & 7) + ((lane >> 4) << 3);
    const uint32_t bSel = (uint32_t)(((lane >> 3) & 1) * 16);
    uint32_t bOffB[2];
#pragma unroll
    for (int p = 0; p < 2; p++) bOffB[p] = (uint32_t)((bN + p * 16) * ROWB) + bSel;

    float acc[4][4][4];
#pragma unroll
    for (int mi = 0; mi < 4; mi++)
#pragma unroll
        for (int ni = 0; ni < 4; ni++)
#pragma unroll
            for (int r = 0; r < 4; r++) acc[mi][ni][r] = 0.f;

#pragma unroll
    for (int pc = 0; pc < 3; pc++) {
        uint32_t st = base + pc * GSTAGE;
        const size_t k0 = (size_t)pc * BKC;
        cp16(st + ldDst0,         g_xh  + aBase0 + k0);
        cp16(st + ldDst1,         g_xh  + aBase1 + k0);
        cp16(st + GTILE + ldDst0, g_Whi + bBase0 + k0);
        cp16(st + GTILE + ldDst1, g_Whi + bBase1 + k0);
        asm volatile("cp.async.commit_group;" ::: "memory");
    }

    for (int kc = 0; kc < NCHUNK; ++kc) {
        if (kc + 2 < NCHUNK) {
            asm volatile("cp.async.wait_group 2;" ::: "memory");
        } else if (kc + 1 < NCHUNK) {
            asm volatile("cp.async.wait_group 1;" ::: "memory");
        } else {
            asm volatile("cp.async.wait_group 0;" ::: "memory");
        }
        __syncthreads();

        if (kc + 3 < NCHUNK) {
            uint32_t st = base + ((kc + 3) % NSTAGE) * GSTAGE;
            const size_t k0 = (size_t)(kc + 3) * BKC;
            cp16(st + ldDst0,         g_xh  + aBase0 + k0);
            cp16(st + ldDst1,         g_xh  + aBase1 + k0);
            cp16(st + GTILE + ldDst0, g_Whi + bBase0 + k0);
            cp16(st + GTILE + ldDst1, g_Whi + bBase1 + k0);
            asm volatile("cp.async.commit_group;" ::: "memory");
        }

        const uint32_t stCur = base + (kc % NSTAGE) * GSTAGE;
#pragma unroll
        for (int ks = 0; ks < 2; ks++) {
            const uint32_t ko = ks * 32;
            uint32_t bh[2][4];
#pragma unroll
            for (int p = 0; p < 2; p++)
                ldsm_x4(bh[p], stCur + GTILE + bOffB[p] + ko);
#pragma unroll
            for (int mi = 0; mi < 4; mi++) {
                uint32_t ah[4];
                ldsm_x4(ah, stCur + aOffB[mi] + ko);
#pragma unroll
                for (int ni = 0; ni < 4; ni++) {
                    const int p = ni >> 1, h = (ni & 1) * 2;
                    mma_f16(acc[mi][ni], ah, &bh[p][h]);
                }
            }
        }
    }

    const bool isMlp = (nBase >= 512);
    const int rBase = tileM + warp_m * 64 + (lane >> 2);
    const int cBase = nBase + warp_n * 32 + 2 * (lane & 3);
#pragma unroll
    for (int mi = 0; mi < 4; mi++) {
#pragma unroll
        for (int half = 0; half < 2; half++) {
            const int row = rBase + mi * 16 + half * 8;
            if (row >= M) continue;
#pragma unroll
            for (int ni = 0; ni < 4; ni++) {
                const int col = cBase + ni * 8;
                float v0 = acc[mi][ni][half * 2 + 0];
                float v1 = acc[mi][ni][half * 2 + 1];
                if (isMlp) {
                    v0 = tanhf(v0 + mlp1_b[col - 512]);
                    v1 = tanhf(v1 + mlp1_b[col - 511]);
                    *reinterpret_cast<float2*>(g_C1m + (size_t)row * 256 + (col - 512)) =
                        make_float2(v0, v1);
                } else {
                    *reinterpret_cast<__half2*>(g_C1h + (size_t)row * 512 + col) =
                        __floats2half2_rn(v0, v1);
                }
            }
        }
    }
}

// ---------------- gather_att v3: one warp per (node,branch), 8 units/thread ----------------
// 4 nodes per 256-thread block. N_NODES = 50000 = 4*12500 exactly (no guards).
#define NPB 4
__global__ __launch_bounds__(256)
void gather_att(const float* __restrict__ b1r1,
                const float* __restrict__ b1r2,
                const float* __restrict__ af) {
    const int t = threadIdx.x;
    const int nodeLocal = t >> 6;                    // 0..3
    const int node = blockIdx.x * NPB + nodeLocal;
    const int br = (t >> 5) & 1;                     // 0: adj/v1, 1: s/v2
    const int lane = t & 31;
    const int u0 = lane * 8;                         // 8 units per thread

    __shared__ float sv2[NPB][256];
    __shared__ float red[NPB][2][3];

    float acc[8] = {0.f, 0.f, 0.f, 0.f, 0.f, 0.f, 0.f, 0.f};
    {
        const int n = min(br ? g_cnt_s[node] : g_cnt_adj[node], ECAP);
        const float2* eb = (br ? g_edge_s : g_edge_adj) + (size_t)node * ECAP;
        const __half* basep = g_C1h + br * 256 + u0;
        float2 ev = (n > 0) ? __ldg(eb) : make_float2(0.f, 0.f);
        for (int e = 0; e < n; e++) {
            float2 evn = (e + 1 < n) ? __ldg(eb + e + 1) : ev;   // prefetch next edge
            int c = __float_as_int(ev.x);
            const float w = ev.y;
            uint4 hv = *reinterpret_cast<const uint4*>(basep + (size_t)c * 512);
            const __half2* hp = reinterpret_cast<const __half2*>(&hv);
            float2 f0 = __half22float2(hp[0]);
            float2 f1 = __half22float2(hp[1]);
            float2 f2 = __half22float2(hp[2]);
            float2 f3 = __half22float2(hp[3]);
            acc[0] += w * f0.x; acc[1] += w * f0.y;
            acc[2] += w * f1.x; acc[3] += w * f1.y;
            acc[4] += w * f2.x; acc[5] += w * f2.y;
            acc[6] += w * f3.x; acc[7] += w * f3.y;
            ev = evn;
        }
        const float* bias = br ? b1r2 : b1r1;
#pragma unroll
        for (int k = 0; k < 8; k++) acc[k] += bias[u0 + k];
    }

    float v3[8];
    if (br == 0) {
        float4 a = *reinterpret_cast<const float4*>(g_C1m + (size_t)node * 256 + u0);
        float4 b = *reinterpret_cast<const float4*>(g_C1m + (size_t)node * 256 + u0 + 4);
        v3[0] = a.x; v3[1] = a.y; v3[2] = a.z; v3[3] = a.w;
        v3[4] = b.x; v3[5] = b.y; v3[6] = b.z; v3[7] = b.w;
    } else {
        // stash v2 for the br==0 warp
#pragma unroll
        for (int k = 0; k < 8; k++) sv2[nodeLocal][u0 + k] = acc[k];
    }

    // attention logit partials
    float p0 = 0.f, p1 = 0.f, p2 = 0.f;
#pragma unroll
    for (int k = 0; k < 8; k++) {
        const int r = br * 256 + u0 + k;
        p0 += acc[k] * af[r * 3 + 0];
        p1 += acc[k] * af[r * 3 + 1];
        p2 += acc[k] * af[r * 3 + 2];
    }
    if (br == 0) {
#pragma unroll
        for (int k = 0; k < 8; k++) {
            const int r = 512 + u0 + k;
            p0 += v3[k] * af[r * 3 + 0];
            p1 += v3[k] * af[r * 3 + 1];
            p2 += v3[k] * af[r * 3 + 2];
        }
    }
#pragma unroll
    for (int off = 16; off; off >>= 1) {
        p0 += __shfl_xor_sync(0xffffffffu, p0, off);
        p1 += __shfl_xor_sync(0xffffffffu, p1, off);
        p2 += __shfl_xor_sync(0xffffffffu, p2, off);
    }
    if (lane == 0) {
        red[nodeLocal][br][0] = p0;
        red[nodeLocal][br][1] = p1;
        red[nodeLocal][br][2] = p2;
    }
    __syncthreads();

    if (br == 0) {
        float a0 = fabsf(red[nodeLocal][0][0] + red[nodeLocal][1][0]);
        float a1 = fabsf(red[nodeLocal][0][1] + red[nodeLocal][1][1]);
        float a2 = fabsf(red[nodeLocal][0][2] + red[nodeLocal][1][2]);
        float m = fmaxf(a0, fmaxf(a1, a2));
        float e0 = __expf(a0 - m), e1 = __expf(a1 - m), e2 = __expf(a2 - m);
        float inv = 1.0f / (e0 + e1 + e2);
        float w0 = e0 * inv, w1 = e1 * inv, w2 = e2 * inv;

        float x1[8];
#pragma unroll
        for (int k = 0; k < 8; k++)
            x1[k] = acc[k] * w0 + sv2[nodeLocal][u0 + k] * w1 + v3[k] * w2;

        float* dst = g_X1 + (size_t)node * 256 + u0;
        *reinterpret_cast<float4*>(dst)     = make_float4(x1[0], x1[1], x1[2], x1[3]);
        *reinterpret_cast<float4*>(dst + 4) = make_float4(x1[4], x1[5], x1[6], x1[7]);
    }
}

// ---------------- GEMM2 fused: Z2 (r1,r2 cols) + out init ----------------
__global__ void gemm2_out(const float* __restrict__ b2r1,
                          const float* __restrict__ b2r2,
                          const float* __restrict__ mlp2_b,
                          float* __restrict__ out, int M) {
    __shared__ float Ws[256 * 6];
    for (int t = threadIdx.x; t < 256 * 6; t += blockDim.x) Ws[t] = g_W2[t];
    __syncthreads();

    int warp = threadIdx.x >> 5, lane = threadIdx.x & 31;
    int row = blockIdx.x * 8 + warp;
    if (row >= M) return;

    float acc[6] = {0.f, 0.f, 0.f, 0.f, 0.f, 0.f};
    const float* xr = g_X1 + (size_t)row * 256;
    for (int k = lane; k < 256; k += 32) {
        float xv = xr[k];
#pragma unroll
        for (int j = 0; j < 6; j++) acc[j] = fmaf(xv, Ws[k * 6 + j], acc[j]);
    }
#pragma unroll
    for (int off = 16; off; off >>= 1)
#pragma unroll
        for (int j = 0; j < 6; j++) acc[j] += __shfl_xor_sync(0xffffffffu, acc[j], off);

    if (lane == 0) {
        float* z = g_Z2 + (size_t)row * 4;
        z[0] = acc[0]; z[1] = acc[1]; z[2] = acc[2]; z[3] = acc[3];
        out[row * 2 + 0] = b2r1[0] + b2r2[0] + tanhf(acc[4] + mlp2_b[0]);
        out[row * 2 + 1] = b2r1[1] + b2r2[1] + tanhf(acc[5] + mlp2_b[1]);
    }
}

// ---------------- layer-2 aggregation: warp-per-node gather, no atomics ----------------
__global__ __launch_bounds__(256)
void gather2_out(float* __restrict__ out, int M) {
    const int warp = threadIdx.x >> 5, lane = threadIdx.x & 31;
    const int i = blockIdx.x * 8 + warp;
    if (i >= M) return;

    float s0 = 0.f, s1 = 0.f;
    {
        const int n = min(g_cnt_adj[i], ECAP);
        const float2* eb = g_edge_adj + (size_t)i * ECAP;
        for (int e = lane; e < n; e += 32) {
            float2 ev = __ldg(eb + e);
            int c = __float_as_int(ev.x);
            float2 z = *reinterpret_cast<const float2*>(g_Z2 + (size_t)c * 4);
            s0 += ev.y * z.x;
            s1 += ev.y * z.y;
        }
    }
    {
        const int n = min(g_cnt_s[i], ECAP);
        const float2* eb = g_edge_s + (size_t)i * ECAP;
        for (int e = lane; e < n; e += 32) {
            float2 ev = __ldg(eb + e);
            int c = __float_as_int(ev.x);
            float2 z = *reinterpret_cast<const float2*>(g_Z2 + (size_t)c * 4 + 2);
            s0 += ev.y * z.x;
            s1 += ev.y * z.y;
        }
    }
#pragma unroll
    for (int off = 16; off; off >>= 1) {
        s0 += __shfl_xor_sync(0xffffffffu, s0, off);
        s1 += __shfl_xor_sync(0xffffffffu, s1, off);
    }
    if (lane == 0) {
        out[i * 2 + 0] += s0;
        out[i * 2 + 1] += s1;
    }
}

// ---------------- launch ----------------
extern "C" void kernel_launch(void* const* d_in, const int* in_sizes, int n_in,
                              void* d_out, int out_size) {
    const float* x        = (const float*)d_in[0];
    const int*   adj_rows = (const int*)d_in[1];
    const int*   adj_cols = (const int*)d_in[2];
    const float* adj_vals = (const float*)d_in[3];
    const int*   s_rows   = (const int*)d_in[4];
    const int*   s_cols   = (const int*)d_in[5];
    const float* s_vals   = (const float*)d_in[6];
    const float* W1r1     = (const float*)d_in[7];
    const float* b1r1     = (const float*)d_in[8];
    const float* W1r2     = (const float*)d_in[9];
    const float* b1r2     = (const float*)d_in[10];
    const float* mlp1_W   = (const float*)d_in[11];
    const float* mlp1_b   = (const float*)d_in[12];
    const float* af1_w    = (const float*)d_in[13];
    const float* W2r1     = (const float*)d_in[14];
    const float* b2r1     = (const float*)d_in[15];
    const float* W2r2     = (const float*)d_in[16];
    const float* b2r2     = (const float*)d_in[17];
    const float* mlp2_W   = (const float*)d_in[18];
    const float* mlp2_b   = (const float*)d_in[19];
    float* out = (float*)d_out;

    const int E = in_sizes[1];
    const int M = N_NODES;

    cudaFuncSetAttribute(gemm1_mma, cudaFuncAttributeMaxDynamicSharedMemorySize, GSMEM);

    // prep
    zero_cnt<<<(N_NODES + 255) / 256, 256>>>();
    const int bucketBlocks = (2 * E + 255) / 256;
    prep_all<<<PREP_FIXED + bucketBlocks, 256>>>(
        x, W1r1, W1r2, mlp1_W, W2r1, W2r2, mlp2_W,
        adj_rows, adj_cols, adj_vals, s_rows, s_cols, s_vals, E);

    // layer 1 big GEMM on tensor cores (HMMA fp16, single product)
    dim3 g1(6, (M + 127) / 128);
    gemm1_mma<<<g1, 256, GSMEM>>>(mlp1_b, M);

    // layer 1 aggregation + attention (warp-per-branch, 8 units/thread)
    gather_att<<<M / NPB, 256>>>(b1r1, b1r2, af1_w);

    // layer 2
    gemm2_out<<<(M + 7) / 8, 256>>>(b2r1, b2r2, mlp2_b, out, M);
    gather2_out<<<(M + 7) / 8, 256>>>(out, M);
}

// round 14
// speedup vs baseline: 1.1741x; 1.0069x over previous
#include <cuda_runtime.h>
#include <cuda_fp16.h>
#include <math.h>
#include <stdint.h>

#define N_NODES 50000
#define D_IN    768
#define NHID    256
#define ECAP    128                      // slots per row-bucket (P(overflow) ~ e^-49)

// ---------------- device scratch (no allocations allowed) ----------------
__device__ __half g_C1h[(size_t)N_NODES * 512];  // branch features (r1 0..255, r2 256..511), fp16
__device__ float  g_C1m[(size_t)N_NODES * 256];  // tanh mlp branch, fp32
__device__ float  g_X1[(size_t)N_NODES * 256];   // fused layer-1 output
__device__ float  g_Z2[(size_t)N_NODES * 4];     // x1 @ [W2r1 | W2r2]
__device__ float  g_W2[256 * 6];                 // packed layer-2 weights (row = hidden unit)

// fp16 operands for the tensor-core GEMM (both rounded to fp16)
__device__ __half g_xh[(size_t)N_NODES * 768];
__device__ __half g_Whi[768 * 768];              // transposed: [n][k] = Wcat[k][n]

// bucketed-CSR edge storage
__device__ int    g_cnt_adj[N_NODES];
__device__ int    g_cnt_s[N_NODES];
__device__ float2 g_edge_adj[(size_t)N_NODES * ECAP];   // .x = col (int bits), .y = val
__device__ float2 g_edge_s[(size_t)N_NODES * ECAP];

// ================= helpers =================
__device__ __forceinline__ uint32_t smem_u32(const void* p) {
    uint32_t a;
    asm("{ .reg .u64 t; cvta.to.shared.u64 t, %1; cvt.u32.u64 %0, t; }" : "=r"(a) : "l"(p));
    return a;
}
__device__ __forceinline__ void cp16(uint32_t dst, const void* src) {
    asm volatile("cp.async.cg.shared.global [%0], [%1], 16;" :: "r"(dst), "l"(src));
}
__device__ __forceinline__ void ldsm_x4(uint32_t* r, uint32_t addr) {
    asm volatile("ldmatrix.sync.aligned.m8n8.x4.shared.b16 {%0,%1,%2,%3}, [%4];"
                 : "=r"(r[0]), "=r"(r[1]), "=r"(r[2]), "=r"(r[3]) : "r"(addr));
}
__device__ __forceinline__ void mma_f16(float* c, const uint32_t* a, const uint32_t* b) {
    asm volatile("mma.sync.aligned.m16n8k16.row.col.f32.f16.f16.f32 "
                 "{%0,%1,%2,%3}, {%4,%5,%6,%7}, {%8,%9}, {%0,%1,%2,%3};"
                 : "+f"(c[0]), "+f"(c[1]), "+f"(c[2]), "+f"(c[3])
                 : "r"(a[0]), "r"(a[1]), "r"(a[2]), "r"(a[3]), "r"(b[0]), "r"(b[1]));
}
__device__ __forceinline__ void row_fma(float* acc, const uint4& hv, float w) {
    const __half2* hp = reinterpret_cast<const __half2*>(&hv);
#pragma unroll
    for (int q = 0; q < 4; q++) {
        float2 f = __half22float2(hp[q]);
        acc[2 * q]     += w * f.x;
        acc[2 * q + 1] += w * f.y;
    }
}

// ---------------- zero edge counters (must precede prep_all) ----------------
__global__ void zero_cnt() {
    int i = blockIdx.x * blockDim.x + threadIdx.x;
    if (i < N_NODES) { g_cnt_adj[i] = 0; g_cnt_s[i] = 0; }
}

// ---------------- fused prep: pack W1, pack W2, split x, build buckets ----------------
#define PW1_BLOCKS 2304                  // 768*768/256
#define PW2_BLOCKS 6
#define SPLIT_BLOCKS 1184
#define PREP_FIXED (PW1_BLOCKS + PW2_BLOCKS + SPLIT_BLOCKS)

__global__ void prep_all(const float* __restrict__ x,
                         const float* __restrict__ W1r1,
                         const float* __restrict__ W1r2,
                         const float* __restrict__ mlp1_W,
                         const float* __restrict__ W2r1,
                         const float* __restrict__ W2r2,
                         const float* __restrict__ mlp2_W,
                         const int* __restrict__ adj_rows,
                         const int* __restrict__ adj_cols,
                         const float* __restrict__ adj_vals,
                         const int* __restrict__ s_rows,
                         const int* __restrict__ s_cols,
                         const float* __restrict__ s_vals,
                         int E) {
    const int b = blockIdx.x;
    const int tid = threadIdx.x;

    if (b < PW1_BLOCKS) {
        int idx = b * 256 + tid;
        int n = idx / 768, k = idx % 768;   // output [n][k] = W[k][n]
        float v;
        if (n < 256)       v = W1r1[k * 256 + n];
        else if (n < 512)  v = W1r2[k * 256 + (n - 256)];
        else               v = mlp1_W[k * 256 + (n - 512)];
        g_Whi[idx] = __float2half_rn(v);
    } else if (b < PW1_BLOCKS + PW2_BLOCKS) {
        int idx = (b - PW1_BLOCKS) * 256 + tid;
        if (idx < 256 * 6) {
            int k = idx / 6, j = idx % 6;
            float v;
            if (j < 2)      v = W2r1[k * 2 + j];
            else if (j < 4) v = W2r2[k * 2 + (j - 2)];
            else            v = mlp2_W[k * 2 + (j - 4)];
            g_W2[idx] = v;
        }
    } else if (b < PREP_FIXED) {
        size_t i = (size_t)(b - PW1_BLOCKS - PW2_BLOCKS) * 256 + tid;
        const size_t stride = (size_t)SPLIT_BLOCKS * 256;
        const size_t total4 = (size_t)N_NODES * 768 / 4;
        const float4* x4 = reinterpret_cast<const float4*>(x);
        __half2* out2 = reinterpret_cast<__half2*>(g_xh);
        for (size_t j = i; j < total4; j += stride) {
            float4 v = x4[j];
            out2[2 * j + 0] = __floats2half2_rn(v.x, v.y);
            out2[2 * j + 1] = __floats2half2_rn(v.z, v.w);
        }
    } else {
        int idx = (b - PREP_FIXED) * 256 + tid;
        if (idx < E) {
            int r = adj_rows[idx];
            int slot = atomicAdd(&g_cnt_adj[r], 1);
            if (slot < ECAP)
                g_edge_adj[(size_t)r * ECAP + slot] =
                    make_float2(__int_as_float(adj_cols[idx]), adj_vals[idx]);
        } else if (idx < 2 * E) {
            int j = idx - E;
            int r = s_rows[j];
            int slot = atomicAdd(&g_cnt_s[r], 1);
            if (slot < ECAP)
                g_edge_s[(size_t)r * ECAP + slot] =
                    make_float2(__int_as_float(s_cols[j]), s_vals[j]);
        }
    }
}

// ================= GEMM1 via mma.sync (HMMA fp16, single product, BK=32) =================
#define BKC 32
#define ROWB 80
#define GTILE (128 * ROWB)
#define GSTAGE (2 * GTILE)
#define NSTAGE 4
#define GSMEM  (NSTAGE * GSTAGE)
#define NCHUNK (768 / BKC)

__global__ __launch_bounds__(256, 2)
void gemm1_mma(const float* __restrict__ mlp1_b, int M) {
    extern __shared__ char dsm[];
    const uint32_t base = smem_u32(dsm);

    const int tid = threadIdx.x;
    const int lane = tid & 31, wid = tid >> 5;
    const int warp_m = wid >> 2;
    const int warp_n = wid & 3;
    const int tileM = blockIdx.y * 128;
    const int nBase = blockIdx.x * 128;

    const int ldRow = tid >> 2;
    const int ldC = tid & 3;
    int rA0 = tileM + ldRow;      if (rA0 >= M) rA0 = M - 1;
    int rA1 = tileM + ldRow + 64; if (rA1 >= M) rA1 = M - 1;
    const uint32_t ldDst0 = ldRow * ROWB + ldC * 16;
    const uint32_t ldDst1 = (ldRow + 64) * ROWB + ldC * 16;
    const size_t aBase0 = (size_t)rA0 * 768 + ldC * 8;
    const size_t aBase1 = (size_t)rA1 * 768 + ldC * 8;
    const size_t bBase0 = (size_t)(nBase + ldRow) * 768 + ldC * 8;
    const size_t bBase1 = (size_t)(nBase + ldRow + 64) * 768 + ldC * 8;

    const int aRow = warp_m * 64 + (lane & 15);
    const uint32_t aSel = (uint32_t)((lane >> 4) * 16);
    uint32_t aOffB[4];
#pragma unroll
    for (int mi = 0; mi < 4; mi++) aOffB[mi] = (uint32_t)((aRow + mi * 16) * ROWB) + aSel;
    const int bN = warp_n * 32 + (lane & 7) + ((lane >> 4) << 3);
    const uint32_t bSel = (uint32_t)(((lane >> 3) & 1) * 16);
    uint32_t bOffB[2];
#pragma unroll
    for (int p = 0; p < 2; p++) bOffB[p] = (uint32_t)((bN + p * 16) * ROWB) + bSel;

    float acc[4][4][4];
#pragma unroll
    for (int mi = 0; mi < 4; mi++)
#pragma unroll
        for (int ni = 0; ni < 4; ni++)
#pragma unroll
            for (int r = 0; r < 4; r++) acc[mi][ni][r] = 0.f;

#pragma unroll
    for (int pc = 0; pc < 3; pc++) {
        uint32_t st = base + pc * GSTAGE;
        const size_t k0 = (size_t)pc * BKC;
        cp16(st + ldDst0,         g_xh  + aBase0 + k0);
        cp16(st + ldDst1,         g_xh  + aBase1 + k0);
        cp16(st + GTILE + ldDst0, g_Whi + bBase0 + k0);
        cp16(st + GTILE + ldDst1, g_Whi + bBase1 + k0);
        asm volatile("cp.async.commit_group;" ::: "memory");
    }

    for (int kc = 0; kc < NCHUNK; ++kc) {
        if (kc + 2 < NCHUNK) {
            asm volatile("cp.async.wait_group 2;" ::: "memory");
        } else if (kc + 1 < NCHUNK) {
            asm volatile("cp.async.wait_group 1;" ::: "memory");
        } else {
            asm volatile("cp.async.wait_group 0;" ::: "memory");
        }
        __syncthreads();

        if (kc + 3 < NCHUNK) {
            uint32_t st = base + ((kc + 3) % NSTAGE) * GSTAGE;
            const size_t k0 = (size_t)(kc + 3) * BKC;
            cp16(st + ldDst0,         g_xh  + aBase0 + k0);
            cp16(st + ldDst1,         g_xh  + aBase1 + k0);
            cp16(st + GTILE + ldDst0, g_Whi + bBase0 + k0);
            cp16(st + GTILE + ldDst1, g_Whi + bBase1 + k0);
            asm volatile("cp.async.commit_group;" ::: "memory");
        }

        const uint32_t stCur = base + (kc % NSTAGE) * GSTAGE;
#pragma unroll
        for (int ks = 0; ks < 2; ks++) {
            const uint32_t ko = ks * 32;
            uint32_t bh[2][4];
#pragma unroll
            for (int p = 0; p < 2; p++)
                ldsm_x4(bh[p], stCur + GTILE + bOffB[p] + ko);
#pragma unroll
            for (int mi = 0; mi < 4; mi++) {
                uint32_t ah[4];
                ldsm_x4(ah, stCur + aOffB[mi] + ko);
#pragma unroll
                for (int ni = 0; ni < 4; ni++) {
                    const int p = ni >> 1, h = (ni & 1) * 2;
                    mma_f16(acc[mi][ni], ah, &bh[p][h]);
                }
            }
        }
    }

    const bool isMlp = (nBase >= 512);
    const int rBase = tileM + warp_m * 64 + (lane >> 2);
    const int cBase = nBase + warp_n * 32 + 2 * (lane & 3);
#pragma unroll
    for (int mi = 0; mi < 4; mi++) {
#pragma unroll
        for (int half = 0; half < 2; half++) {
            const int row = rBase + mi * 16 + half * 8;
            if (row >= M) continue;
#pragma unroll
            for (int ni = 0; ni < 4; ni++) {
                const int col = cBase + ni * 8;
                float v0 = acc[mi][ni][half * 2 + 0];
                float v1 = acc[mi][ni][half * 2 + 1];
                if (isMlp) {
                    v0 = tanhf(v0 + mlp1_b[col - 512]);
                    v1 = tanhf(v1 + mlp1_b[col - 511]);
                    *reinterpret_cast<float2*>(g_C1m + (size_t)row * 256 + (col - 512)) =
                        make_float2(v0, v1);
                } else {
                    *reinterpret_cast<__half2*>(g_C1h + (size_t)row * 512 + col) =
                        __floats2half2_rn(v0, v1);
                }
            }
        }
    }
}

// ---------------- gather_att v4: warp per (node,branch), 8 units/thread, 2-edge unroll ----------------
#define NPB 4
__global__ __launch_bounds__(256)
void gather_att(const float* __restrict__ b1r1,
                const float* __restrict__ b1r2,
                const float* __restrict__ af) {
    const int t = threadIdx.x;
    const int nodeLocal = t >> 6;                    // 0..3
    const int node = blockIdx.x * NPB + nodeLocal;
    const int br = (t >> 5) & 1;                     // 0: adj/v1, 1: s/v2
    const int lane = t & 31;
    const int u0 = lane * 8;                         // 8 units per thread

    __shared__ float sv2[NPB][256];
    __shared__ float red[NPB][2][3];

    float acc[8] = {0.f, 0.f, 0.f, 0.f, 0.f, 0.f, 0.f, 0.f};
    {
        const int n = min(br ? g_cnt_s[node] : g_cnt_adj[node], ECAP);
        const float2* eb = (br ? g_edge_s : g_edge_adj) + (size_t)node * ECAP;
        const __half* basep = g_C1h + br * 256 + u0;

        int e = 0;
        for (; e + 1 < n; e += 2) {
            // both edges' metadata in one LDG.128 (bucket is 16B-aligned)
            float4 ep = __ldg(reinterpret_cast<const float4*>(eb + e));
            const int c0 = __float_as_int(ep.x);
            const int c1 = __float_as_int(ep.z);
            // issue both row loads before consuming either (MLP=2)
            uint4 hv0 = __ldg(reinterpret_cast<const uint4*>(basep + (size_t)c0 * 512));
            uint4 hv1 = __ldg(reinterpret_cast<const uint4*>(basep + (size_t)c1 * 512));
            row_fma(acc, hv0, ep.y);
            row_fma(acc, hv1, ep.w);
        }
        if (e < n) {
            float2 ev = __ldg(eb + e);
            uint4 hv = __ldg(reinterpret_cast<const uint4*>(
                                 basep + (size_t)__float_as_int(ev.x) * 512));
            row_fma(acc, hv, ev.y);
        }
        const float* bias = br ? b1r2 : b1r1;
#pragma unroll
        for (int k = 0; k < 8; k++) acc[k] += bias[u0 + k];
    }

    float v3[8];
    if (br == 0) {
        float4 a = *reinterpret_cast<const float4*>(g_C1m + (size_t)node * 256 + u0);
        float4 b = *reinterpret_cast<const float4*>(g_C1m + (size_t)node * 256 + u0 + 4);
        v3[0] = a.x; v3[1] = a.y; v3[2] = a.z; v3[3] = a.w;
        v3[4] = b.x; v3[5] = b.y; v3[6] = b.z; v3[7] = b.w;
    } else {
#pragma unroll
        for (int k = 0; k < 8; k++) sv2[nodeLocal][u0 + k] = acc[k];
    }

    // attention logit partials
    float p0 = 0.f, p1 = 0.f, p2 = 0.f;
#pragma unroll
    for (int k = 0; k < 8; k++) {
        const int r = br * 256 + u0 + k;
        p0 += acc[k] * af[r * 3 + 0];
        p1 += acc[k] * af[r * 3 + 1];
        p2 += acc[k] * af[r * 3 + 2];
    }
    if (br == 0) {
#pragma unroll
        for (int k = 0; k < 8; k++) {
            const int r = 512 + u0 + k;
            p0 += v3[k] * af[r * 3 + 0];
            p1 += v3[k] * af[r * 3 + 1];
            p2 += v3[k] * af[r * 3 + 2];
        }
    }
#pragma unroll
    for (int off = 16; off; off >>= 1) {
        p0 += __shfl_xor_sync(0xffffffffu, p0, off);
        p1 += __shfl_xor_sync(0xffffffffu, p1, off);
        p2 += __shfl_xor_sync(0xffffffffu, p2, off);
    }
    if (lane == 0) {
        red[nodeLocal][br][0] = p0;
        red[nodeLocal][br][1] = p1;
        red[nodeLocal][br][2] = p2;
    }
    __syncthreads();

    if (br == 0) {
        float a0 = fabsf(red[nodeLocal][0][0] + red[nodeLocal][1][0]);
        float a1 = fabsf(red[nodeLocal][0][1] + red[nodeLocal][1][1]);
        float a2 = fabsf(red[nodeLocal][0][2] + red[nodeLocal][1][2]);
        float m = fmaxf(a0, fmaxf(a1, a2));
        float e0 = __expf(a0 - m), e1 = __expf(a1 - m), e2 = __expf(a2 - m);
        float inv = 1.0f / (e0 + e1 + e2);
        float w0 = e0 * inv, w1 = e1 * inv, w2 = e2 * inv;

        float x1[8];
#pragma unroll
        for (int k = 0; k < 8; k++)
            x1[k] = acc[k] * w0 + sv2[nodeLocal][u0 + k] * w1 + v3[k] * w2;

        float* dst = g_X1 + (size_t)node * 256 + u0;
        *reinterpret_cast<float4*>(dst)     = make_float4(x1[0], x1[1], x1[2], x1[3]);
        *reinterpret_cast<float4*>(dst + 4) = make_float4(x1[4], x1[5], x1[6], x1[7]);
    }
}

// ---------------- GEMM2 fused: Z2 (r1,r2 cols) + out init ----------------
__global__ void gemm2_out(const float* __restrict__ b2r1,
                          const float* __restrict__ b2r2,
                          const float* __restrict__ mlp2_b,
                          float* __restrict__ out, int M) {
    __shared__ float Ws[256 * 6];
    for (int t = threadIdx.x; t < 256 * 6; t += blockDim.x) Ws[t] = g_W2[t];
    __syncthreads();

    int warp = threadIdx.x >> 5, lane = threadIdx.x & 31;
    int row = blockIdx.x * 8 + warp;
    if (row >= M) return;

    float acc[6] = {0.f, 0.f, 0.f, 0.f, 0.f, 0.f};
    const float* xr = g_X1 + (size_t)row * 256;
    for (int k = lane; k < 256; k += 32) {
        float xv = xr[k];
#pragma unroll
        for (int j = 0; j < 6; j++) acc[j] = fmaf(xv, Ws[k * 6 + j], acc[j]);
    }
#pragma unroll
    for (int off = 16; off; off >>= 1)
#pragma unroll
        for (int j = 0; j < 6; j++) acc[j] += __shfl_xor_sync(0xffffffffu, acc[j], off);

    if (lane == 0) {
        float* z = g_Z2 + (size_t)row * 4;
        z[0] = acc[0]; z[1] = acc[1]; z[2] = acc[2]; z[3] = acc[3];
        out[row * 2 + 0] = b2r1[0] + b2r2[0] + tanhf(acc[4] + mlp2_b[0]);
        out[row * 2 + 1] = b2r1[1] + b2r2[1] + tanhf(acc[5] + mlp2_b[1]);
    }
}

// ---------------- layer-2 aggregation: warp-per-node gather, no atomics ----------------
__global__ __launch_bounds__(256)
void gather2_out(float* __restrict__ out, int M) {
    const int warp = threadIdx.x >> 5, lane = threadIdx.x & 31;
    const int i = blockIdx.x * 8 + warp;
    if (i >= M) return;

    float s0 = 0.f, s1 = 0.f;
    {
        const int n = min(g_cnt_adj[i], ECAP);
        const float2* eb = g_edge_adj + (size_t)i * ECAP;
        for (int e = lane; e < n; e += 32) {
            float2 ev = __ldg(eb + e);
            int c = __float_as_int(ev.x);
            float2 z = *reinterpret_cast<const float2*>(g_Z2 + (size_t)c * 4);
            s0 += ev.y * z.x;
            s1 += ev.y * z.y;
        }
    }
    {
        const int n = min(g_cnt_s[i], ECAP);
        const float2* eb = g_edge_s + (size_t)i * ECAP;
        for (int e = lane; e < n; e += 32) {
            float2 ev = __ldg(eb + e);
            int c = __float_as_int(ev.x);
            float2 z = *reinterpret_cast<const float2*>(g_Z2 + (size_t)c * 4 + 2);
            s0 += ev.y * z.x;
            s1 += ev.y * z.y;
        }
    }
#pragma unroll
    for (int off = 16; off; off >>= 1) {
        s0 += __shfl_xor_sync(0xffffffffu, s0, off);
        s1 += __shfl_xor_sync(0xffffffffu, s1, off);
    }
    if (lane == 0) {
        out[i * 2 + 0] += s0;
        out[i * 2 + 1] += s1;
    }
}

// ---------------- launch ----------------
extern "C" void kernel_launch(void* const* d_in, const int* in_sizes, int n_in,
                              void* d_out, int out_size) {
    const float* x        = (const float*)d_in[0];
    const int*   adj_rows = (const int*)d_in[1];
    const int*   adj_cols = (const int*)d_in[2];
    const float* adj_vals = (const float*)d_in[3];
    const int*   s_rows   = (const int*)d_in[4];
    const int*   s_cols   = (const int*)d_in[5];
    const float* s_vals   = (const float*)d_in[6];
    const float* W1r1     = (const float*)d_in[7];
    const float* b1r1     = (const float*)d_in[8];
    const float* W1r2     = (const float*)d_in[9];
    const float* b1r2     = (const float*)d_in[10];
    const float* mlp1_W   = (const float*)d_in[11];
    const float* mlp1_b   = (const float*)d_in[12];
    const float* af1_w    = (const float*)d_in[13];
    const float* W2r1     = (const float*)d_in[14];
    const float* b2r1     = (const float*)d_in[15];
    const float* W2r2     = (const float*)d_in[16];
    const float* b2r2     = (const float*)d_in[17];
    const float* mlp2_W   = (const float*)d_in[18];
    const float* mlp2_b   = (const float*)d_in[19];
    float* out = (float*)d_out;

    const int E = in_sizes[1];
    const int M = N_NODES;

    cudaFuncSetAttribute(gemm1_mma, cudaFuncAttributeMaxDynamicSharedMemorySize, GSMEM);

    // prep
    zero_cnt<<<(N_NODES + 255) / 256, 256>>>();
    const int bucketBlocks = (2 * E + 255) / 256;
    prep_all<<<PREP_FIXED + bucketBlocks, 256>>>(
        x, W1r1, W1r2, mlp1_W, W2r1, W2r2, mlp2_W,
        adj_rows, adj_cols, adj_vals, s_rows, s_cols, s_vals, E);

    // layer 1 big GEMM on tensor cores (HMMA fp16, single product)
    dim3 g1(6, (M + 127) / 128);
    gemm1_mma<<<g1, 256, GSMEM>>>(mlp1_b, M);

    // layer 1 aggregation + attention (warp-per-branch, 2-edge unroll)
    gather_att<<<M / NPB, 256>>>(b1r1, b1r2, af1_w);

    // layer 2
    gemm2_out<<<(M + 7) / 8, 256>>>(b2r1, b2r2, mlp2_b, out, M);
    gather2_out<<<(M + 7) / 8, 256>>>(out, M);
}